// round 1
// baseline (speedup 1.0000x reference)
#include <cuda_runtime.h>

// Problem constants
#define H_   128
#define W_   128
#define C_   32
#define B_   4
#define OH_  120
#define OW_  120
#define OCH_ 100   // offset channels = 25 taps * 2 (dy,dx) * 2 groups
#define F_   64

// Scratch for offset-conv output: (B, OH, OW, 100) fp32  (~23 MB device global)
__device__ float g_offbuf[(size_t)B_ * OH_ * OW_ * OCH_];

// ---------------------------------------------------------------------------
// Kernel A: dense dilated 5x5 conv producing the 100 offset channels.
// Tile: 8 px in x, 4 px in y (32 px/block). GEMM: [100 ch x 32 px], K = 25*32.
// 200 threads, thread tile 4ch x 4px (16 fp32 accumulators).
// ---------------------------------------------------------------------------
__global__ __launch_bounds__(200)
void offset_conv_kernel(const float* __restrict__ vol,
                        const float* __restrict__ w_off,
                        const float* __restrict__ b_off)
{
    __shared__ float patch[12 * 16 * 32];  // input rows oy0..oy0+11, cols ox0..+15  (24 KB)
    __shared__ float ws[32 * 100];         // per-tap weights [c][ch]                (12.8 KB)
    __shared__ float Bs[32 * 33];          // per-tap B-matrix [c][px], pad 33       (4.2 KB)

    const int tid = threadIdx.x;
    const int ox0 = blockIdx.x * 8;
    const int oy0 = blockIdx.y * 4;
    const int b   = blockIdx.z;

    // Load patch: 12 rows x 16 cols x 32 ch = 1536 float4, fully coalesced.
    {
        for (int idx = tid; idx < 1536; idx += 200) {
            int row = idx >> 7;          // 128 float4 per row (16 x * 8 c4)
            int rem = idx & 127;
            const float4* src = reinterpret_cast<const float4*>(
                vol + ((size_t)((b * H_ + oy0 + row) * W_ + ox0)) * C_);
            reinterpret_cast<float4*>(patch)[row * 128 + rem] = src[rem];
        }
    }

    const int tm = tid % 25;   // channel group: ch = 4*tm   (0..96)
    const int tn = tid / 25;   // pixel group:  p  = 4*tn   (tn 0..7)

    float acc[4][4];
#pragma unroll
    for (int i = 0; i < 4; ++i)
#pragma unroll
        for (int j = 0; j < 4; ++j) acc[i][j] = 0.0f;

    for (int k = 0; k < 25; ++k) {
        __syncthreads();  // protects patch load (k=0) and prior-tap smem reads
        // Stage per-tap weights: ws[c][ch] = w_off[k, c, ch]   (ch contiguous -> coalesced)
        for (int idx = tid; idx < 3200; idx += 200) {
            int c  = idx / 100;
            int ch = idx - c * 100;
            ws[c * 100 + ch] = w_off[(k * 32 + c) * 100 + ch];
        }
        // Stage Bs[c][p]: lanes span c (conflict-free reads), pad-33 writes (conflict-free)
        const int fy2 = (k / 5) * 2, fx2 = (k % 5) * 2;
        for (int idx = tid; idx < 1024; idx += 200) {
            int c = idx & 31;
            int p = idx >> 5;
            int ty = p >> 3, tx = p & 7;
            Bs[c * 33 + p] = patch[((ty + fy2) * 16 + (tx + fx2)) * 32 + c];
        }
        __syncthreads();

#pragma unroll 8
        for (int c = 0; c < 32; ++c) {
            float4 av = *reinterpret_cast<const float4*>(&ws[c * 100 + 4 * tm]);
            float a[4] = {av.x, av.y, av.z, av.w};
            float bb[4];
#pragma unroll
            for (int j = 0; j < 4; ++j) bb[j] = Bs[c * 33 + 4 * tn + j];
#pragma unroll
            for (int i = 0; i < 4; ++i)
#pragma unroll
                for (int j = 0; j < 4; ++j)
                    acc[i][j] = fmaf(a[i], bb[j], acc[i][j]);
        }
    }

    // Epilogue: add bias, vectorized store (ch0 multiple of 4 -> 16B aligned)
    const int ch0 = 4 * tm;
    const float bo0 = b_off[ch0], bo1 = b_off[ch0 + 1], bo2 = b_off[ch0 + 2], bo3 = b_off[ch0 + 3];
#pragma unroll
    for (int j = 0; j < 4; ++j) {
        int p  = 4 * tn + j;
        int oy = oy0 + (p >> 3), ox = ox0 + (p & 7);
        float4 r = make_float4(acc[0][j] + bo0, acc[1][j] + bo1,
                               acc[2][j] + bo2, acc[3][j] + bo3);
        *reinterpret_cast<float4*>(
            &g_offbuf[((size_t)((b * OH_ + oy) * OW_ + ox)) * OCH_ + ch0]) = r;
    }
}

// ---------------------------------------------------------------------------
// Kernel B: deformable gather + grouped conv.
// Tile: 8 px in x, 4 px in y (32 px/block), 64 threads.
// Per tap k: each thread bilinearly gathers one (px, group) channel row into
// smem, then a 64out x 32px GEMM over C=32 (thread tile 8out x 4px).
// ---------------------------------------------------------------------------
#define SS_P 36     // Ss pixel stride (floats), conflict-free & 16B aligned
#define SS_G 1168   // Ss group stride (floats), 16B aligned, bank-shifted

__global__ __launch_bounds__(64)
void dcn_kernel(const float* __restrict__ vol,
                const float* __restrict__ w_dcn,
                const float* __restrict__ b_dcn,
                float* __restrict__ out)
{
    __shared__ float offS[32 * OCH_];   // offsets for the 32-px tile (12.8 KB)
    __shared__ float wks[32 * 64];      // per-tap weights [c][o]      (8 KB)
    __shared__ float Ss[2 * SS_G];      // sampled [g][p][c]           (9.1 KB)

    const int tid = threadIdx.x;
    const int ox0 = blockIdx.x * 8;
    const int oy0 = blockIdx.y * 4;
    const int b   = blockIdx.z;

    // Stage the tile's offsets
    for (int idx = tid; idx < 32 * OCH_; idx += 64) {
        int p  = idx / OCH_;
        int ch = idx - p * OCH_;
        int oy = oy0 + (p >> 3), ox = ox0 + (p & 7);
        offS[idx] = g_offbuf[((size_t)((b * OH_ + oy) * OW_ + ox)) * OCH_ + ch];
    }

    // GEMM role
    const int om  = tid & 7;    // out group: o = om*8
    const int pn  = tid >> 3;   // px group:  p = pn*4
    const int myg = om >> 2;    // deform group for my outputs (o<32 -> 0, else 1)
    // Gather role: one (px, group) pair per thread
    const int gp = tid >> 1;
    const int gg = tid & 1;
    const float ycen = (float)(oy0 + (gp >> 3) + 4);
    const float xcen = (float)(ox0 + (gp & 7) + 4);
    const float* volb = vol + (size_t)b * H_ * W_ * C_;

    float acc[8][4];
#pragma unroll
    for (int i = 0; i < 8; ++i)
#pragma unroll
        for (int j = 0; j < 4; ++j) acc[i][j] = 0.0f;

    for (int k = 0; k < 25; ++k) {
        __syncthreads();  // offS ready (k=0) / prior GEMM reads done
        // Stage per-tap weights: wks[c*64+o] = w_dcn[k, c, o] (fully coalesced)
        for (int idx = tid; idx < 2048; idx += 64)
            wks[idx] = w_dcn[k * 2048 + idx];

        // Bilinear gather for my (gp, gg): 32 channels via 8 float4 blends
        {
            const int fy = k / 5, fx = k - fy * 5;
            float offy = offS[gp * OCH_ + k * 4 + gg];
            float offx = offS[gp * OCH_ + k * 4 + 2 + gg];
            float py = ycen + (float)((fy - 2) * 2) + offy;
            float px = xcen + (float)((fx - 2) * 2) + offx;
            py = fminf(fmaxf(py, 0.0f), 127.0f);
            px = fminf(fmaxf(px, 0.0f), 127.0f);
            float y0f = fminf(floorf(py), 126.0f);
            float x0f = fminf(floorf(px), 126.0f);
            float wy = py - y0f, wx = px - x0f;
            int y0 = (int)y0f, x0 = (int)x0f;
            const float4* r00 = reinterpret_cast<const float4*>(
                volb + ((size_t)y0 * W_ + x0) * C_);
            const float4* r10 = reinterpret_cast<const float4*>(
                volb + ((size_t)(y0 + 1) * W_ + x0) * C_);
            float c00 = (1.0f - wy) * (1.0f - wx);
            float c01 = (1.0f - wy) * wx;
            float c10 = wy * (1.0f - wx);
            float c11 = wy * wx;
            float4* dst = reinterpret_cast<float4*>(&Ss[gg * SS_G + gp * SS_P]);
#pragma unroll
            for (int j = 0; j < 8; ++j) {
                float4 v00 = r00[j], v01 = r00[j + 8];
                float4 v10 = r10[j], v11 = r10[j + 8];
                float4 s;
                s.x = fmaf(v00.x, c00, fmaf(v01.x, c01, fmaf(v10.x, c10, v11.x * c11)));
                s.y = fmaf(v00.y, c00, fmaf(v01.y, c01, fmaf(v10.y, c10, v11.y * c11)));
                s.z = fmaf(v00.z, c00, fmaf(v01.z, c01, fmaf(v10.z, c10, v11.z * c11)));
                s.w = fmaf(v00.w, c00, fmaf(v01.w, c01, fmaf(v10.w, c10, v11.w * c11)));
                dst[j] = s;
            }
        }
        __syncthreads();

        // GEMM accumulate over C=32 for this tap
        const float* SsG = &Ss[myg * SS_G];
#pragma unroll 8
        for (int c = 0; c < 32; ++c) {
            float4 a0 = *reinterpret_cast<const float4*>(&wks[c * 64 + om * 8]);
            float4 a1 = *reinterpret_cast<const float4*>(&wks[c * 64 + om * 8 + 4]);
            float a[8] = {a0.x, a0.y, a0.z, a0.w, a1.x, a1.y, a1.z, a1.w};
            float bb[4];
#pragma unroll
            for (int j = 0; j < 4; ++j) bb[j] = SsG[(pn * 4 + j) * SS_P + c];
#pragma unroll
            for (int i = 0; i < 8; ++i)
#pragma unroll
                for (int j = 0; j < 4; ++j)
                    acc[i][j] = fmaf(a[i], bb[j], acc[i][j]);
        }
    }

    // Epilogue: bias + vectorized stores
    const int o0 = om * 8;
    float bo[8];
#pragma unroll
    for (int i = 0; i < 8; ++i) bo[i] = b_dcn[o0 + i];
#pragma unroll
    for (int j = 0; j < 4; ++j) {
        int p  = pn * 4 + j;
        int oy = oy0 + (p >> 3), ox = ox0 + (p & 7);
        float* op = out + ((size_t)((b * OH_ + oy) * OW_ + ox)) * F_ + o0;
        float4 r0 = make_float4(acc[0][j] + bo[0], acc[1][j] + bo[1],
                                acc[2][j] + bo[2], acc[3][j] + bo[3]);
        float4 r1 = make_float4(acc[4][j] + bo[4], acc[5][j] + bo[5],
                                acc[6][j] + bo[6], acc[7][j] + bo[7]);
        *reinterpret_cast<float4*>(op)     = r0;
        *reinterpret_cast<float4*>(op + 4) = r1;
    }
}

// ---------------------------------------------------------------------------
extern "C" void kernel_launch(void* const* d_in, const int* in_sizes, int n_in,
                              void* d_out, int out_size)
{
    const float* vol   = (const float*)d_in[0];  // (4,128,128,32)
    const float* w_off = (const float*)d_in[1];  // (5,5,32,100)
    const float* b_off = (const float*)d_in[2];  // (100,)
    const float* w_dcn = (const float*)d_in[3];  // (25,32,64)
    const float* b_dcn = (const float*)d_in[4];  // (64,)
    float* out = (float*)d_out;                  // (4,120,120,64)

    dim3 gA(OW_ / 8, OH_ / 4, B_);   // (15, 30, 4)
    offset_conv_kernel<<<gA, 200>>>(vol, w_off, b_off);

    dim3 gB(OW_ / 8, OH_ / 4, B_);   // (15, 30, 4)
    dcn_kernel<<<gB, 64>>>(vol, w_dcn, b_dcn, out);
}

// round 2
// speedup vs baseline: 1.5146x; 1.5146x over previous
#include <cuda_runtime.h>

// Problem constants
#define H_   128
#define W_   128
#define C_   32
#define B_   4
#define OH_  120
#define OW_  120
#define OCH_ 100   // offset channels = 25 taps * 2 (dy,dx) * 2 groups
#define F_   64

// Scratch for offset-conv output: (B, OH, OW, 100) fp32  (~23 MB device global)
__device__ float g_offbuf[(size_t)B_ * OH_ * OW_ * OCH_];

// ---------------------------------------------------------------------------
// Kernel A: dense dilated 5x5 conv producing the 100 offset channels.
// Tile: 8 px in x, 4 px in y (32 px/block). GEMM: [100 ch x 32 px], K = 25*32.
// 200 threads, thread tile 4ch x 4px (16 fp32 accumulators).
// (Near fp32-FFMA roof already; unchanged this round.)
// ---------------------------------------------------------------------------
__global__ __launch_bounds__(200)
void offset_conv_kernel(const float* __restrict__ vol,
                        const float* __restrict__ w_off,
                        const float* __restrict__ b_off)
{
    __shared__ float patch[12 * 16 * 32];  // 24 KB
    __shared__ float ws[32 * 100];         // 12.8 KB
    __shared__ float Bs[32 * 33];          // 4.2 KB

    const int tid = threadIdx.x;
    const int ox0 = blockIdx.x * 8;
    const int oy0 = blockIdx.y * 4;
    const int b   = blockIdx.z;

    for (int idx = tid; idx < 1536; idx += 200) {
        int row = idx >> 7;
        int rem = idx & 127;
        const float4* src = reinterpret_cast<const float4*>(
            vol + ((size_t)((b * H_ + oy0 + row) * W_ + ox0)) * C_);
        reinterpret_cast<float4*>(patch)[row * 128 + rem] = src[rem];
    }

    const int tm = tid % 25;
    const int tn = tid / 25;

    float acc[4][4];
#pragma unroll
    for (int i = 0; i < 4; ++i)
#pragma unroll
        for (int jj = 0; jj < 4; ++jj) acc[i][jj] = 0.0f;

    for (int k = 0; k < 25; ++k) {
        __syncthreads();
        for (int idx = tid; idx < 3200; idx += 200) {
            int c  = idx / 100;
            int ch = idx - c * 100;
            ws[c * 100 + ch] = w_off[(k * 32 + c) * 100 + ch];
        }
        const int fy2 = (k / 5) * 2, fx2 = (k % 5) * 2;
        for (int idx = tid; idx < 1024; idx += 200) {
            int c = idx & 31;
            int p = idx >> 5;
            int ty = p >> 3, tx = p & 7;
            Bs[c * 33 + p] = patch[((ty + fy2) * 16 + (tx + fx2)) * 32 + c];
        }
        __syncthreads();

#pragma unroll 8
        for (int c = 0; c < 32; ++c) {
            float4 av = *reinterpret_cast<const float4*>(&ws[c * 100 + 4 * tm]);
            float a[4] = {av.x, av.y, av.z, av.w};
            float bb[4];
#pragma unroll
            for (int jj = 0; jj < 4; ++jj) bb[jj] = Bs[c * 33 + 4 * tn + jj];
#pragma unroll
            for (int i = 0; i < 4; ++i)
#pragma unroll
                for (int jj = 0; jj < 4; ++jj)
                    acc[i][jj] = fmaf(a[i], bb[jj], acc[i][jj]);
        }
    }

    const int ch0 = 4 * tm;
    const float bo0 = b_off[ch0], bo1 = b_off[ch0 + 1], bo2 = b_off[ch0 + 2], bo3 = b_off[ch0 + 3];
#pragma unroll
    for (int jj = 0; jj < 4; ++jj) {
        int p  = 4 * tn + jj;
        int oy = oy0 + (p >> 3), ox = ox0 + (p & 7);
        float4 r = make_float4(acc[0][jj] + bo0, acc[1][jj] + bo1,
                               acc[2][jj] + bo2, acc[3][jj] + bo3);
        *reinterpret_cast<float4*>(
            &g_offbuf[((size_t)((b * OH_ + oy) * OW_ + ox)) * OCH_ + ch0]) = r;
    }
}

// ---------------------------------------------------------------------------
// Kernel B v2: deformable gather + grouped conv.
// Tile: 8y x 8x = 64 px, 128 threads (4 warps), grid (15,15,4).
// Gather: warp-cooperative — per pass, 4 samples x 8 lanes; each LDG.128
//   instruction covers 4 full 128B lines (100% wavefront efficiency). Lane
//   (s, j) ends up owning channels [4j, 4j+4) of sample s; blends locally,
//   one conflict-free STS.128.
// GEMM: 64 out x 64 px over C=32 per tap, thread tile 8 out x 4 px with px
//   strided +16 (bank-conflict-free scalar B reads); weight smem padded +4
//   floats at o=32 (conflict-free LDS.128 A reads).
// ---------------------------------------------------------------------------
#define SS_P   36        // Ss pixel stride (floats)
#define SS_G   2320      // Ss group stride: 64*36 + 16 (bank shift, 16B-aligned)
#define WK_R   68        // wks row stride (64 + 4-pad inserted at o=32)

__global__ __launch_bounds__(128)
void dcn_kernel(const float* __restrict__ vol,
                const float* __restrict__ w_dcn,
                const float* __restrict__ b_dcn,
                float* __restrict__ out)
{
    __shared__ float wks[32 * WK_R];   // per-tap weights, padded   (8.7 KB)
    __shared__ float Ss[2 * SS_G];     // sampled [g][p][c]         (18.6 KB)

    const int tid  = threadIdx.x;
    const int lane = tid & 31;
    const int warp = tid >> 5;
    const int ox0 = blockIdx.x * 8;
    const int oy0 = blockIdx.y * 8;
    const int b   = blockIdx.z;

    // GEMM roles
    const int om  = tid & 7;     // outs: o = om*8 .. +7
    const int pn  = tid >> 3;    // px set {pn, pn+16, pn+32, pn+48}
    const int myg = om >> 2;

    // Gather roles: per pass, warp covers 4 samples x 8 lanes
    const int q = lane >> 3;     // sample-within-pass
    const int j = lane & 7;      // float4 index within 128B line
    const int sBase = warp * 32; // warp's 32 samples (64 px x 2 g = 128 tasks)

    const float* volb = vol + (size_t)b * (H_ * W_ * C_);
    const float* offb = g_offbuf + ((size_t)(b * OH_ + oy0) * OW_ + ox0) * OCH_;

    float acc[8][4];
#pragma unroll
    for (int i = 0; i < 8; ++i)
#pragma unroll
        for (int jj = 0; jj < 4; ++jj) acc[i][jj] = 0.0f;

    for (int k = 0; k < 25; ++k) {
        __syncthreads();  // prior GEMM reads done / first-iter no-op

        // Stage per-tap weights with o>=32 pad (coalesced LDG, conflict-free STS)
        const float* wsrc = w_dcn + k * 2048;
        for (int idx = tid; idx < 2048; idx += 128) {
            int c = idx >> 6, o = idx & 63;
            wks[c * WK_R + o + ((o & 32) >> 3)] = wsrc[idx];
        }

        const int fy = k / 5, fx = k - fy * 5;
        const float dky = (float)((fy - 2) * 2);
        const float dkx = (float)((fx - 2) * 2);

#pragma unroll
        for (int pass = 0; pass < 8; ++pass) {
            int s = sBase + pass * 4 + q;
            int p = s & 63, g = s >> 6;
            int pyi = p >> 3, pxi = p & 7;

            const float* op = offb + (pyi * OW_ + pxi) * OCH_ + k * 4 + g;
            float offy = op[0];
            float offx = op[2];

            float py = (float)(oy0 + pyi + 4) + dky + offy;
            float px = (float)(ox0 + pxi + 4) + dkx + offx;
            py = fminf(fmaxf(py, 0.0f), 127.0f);
            px = fminf(fmaxf(px, 0.0f), 127.0f);
            float y0f = fminf(floorf(py), 126.0f);
            float x0f = fminf(floorf(px), 126.0f);
            float wy = py - y0f, wx = px - x0f;
            int y0 = (int)y0f, x0 = (int)x0f;

            const float4* r0 = reinterpret_cast<const float4*>(
                volb + ((size_t)(y0 * W_ + x0)) * C_);   // 128B-line aligned
            float4 L0 = r0[j];            // (y0  , x0  ) ch 4j..4j+3
            float4 L1 = r0[j + 8];        // (y0  , x0+1)
            float4 L2 = r0[j + 1024];     // (y0+1, x0  )  (+W_*C_ floats)
            float4 L3 = r0[j + 1032];     // (y0+1, x0+1)

            float c00 = (1.0f - wy) * (1.0f - wx);
            float c01 = (1.0f - wy) * wx;
            float c10 = wy * (1.0f - wx);
            float c11 = wy * wx;

            float4 sv;
            sv.x = fmaf(L0.x, c00, fmaf(L1.x, c01, fmaf(L2.x, c10, L3.x * c11)));
            sv.y = fmaf(L0.y, c00, fmaf(L1.y, c01, fmaf(L2.y, c10, L3.y * c11)));
            sv.z = fmaf(L0.z, c00, fmaf(L1.z, c01, fmaf(L2.z, c10, L3.z * c11)));
            sv.w = fmaf(L0.w, c00, fmaf(L1.w, c01, fmaf(L2.w, c10, L3.w * c11)));

            *reinterpret_cast<float4*>(&Ss[g * SS_G + p * SS_P + j * 4]) = sv;
        }
        __syncthreads();

        // GEMM accumulate over C=32 for this tap
        const float* Sg   = Ss + myg * SS_G;
        const float* wrow = wks + om * 8 + ((om & 4) ? 4 : 0);
#pragma unroll
        for (int c = 0; c < 32; ++c) {
            float4 a0 = *reinterpret_cast<const float4*>(&wrow[c * WK_R]);
            float4 a1 = *reinterpret_cast<const float4*>(&wrow[c * WK_R + 4]);
            float a[8] = {a0.x, a0.y, a0.z, a0.w, a1.x, a1.y, a1.z, a1.w};
            float bb[4];
            bb[0] = Sg[(pn     ) * SS_P + c];
            bb[1] = Sg[(pn + 16) * SS_P + c];
            bb[2] = Sg[(pn + 32) * SS_P + c];
            bb[3] = Sg[(pn + 48) * SS_P + c];
#pragma unroll
            for (int i = 0; i < 8; ++i)
#pragma unroll
                for (int jj = 0; jj < 4; ++jj)
                    acc[i][jj] = fmaf(a[i], bb[jj], acc[i][jj]);
        }
    }

    // Epilogue: bias + vectorized stores
    const int o0 = om * 8;
    float bo[8];
#pragma unroll
    for (int i = 0; i < 8; ++i) bo[i] = b_dcn[o0 + i];
#pragma unroll
    for (int jj = 0; jj < 4; ++jj) {
        int p  = pn + jj * 16;
        int oy = oy0 + (p >> 3), ox = ox0 + (p & 7);
        float* opx = out + ((size_t)((b * OH_ + oy) * OW_ + ox)) * F_ + o0;
        float4 r0 = make_float4(acc[0][jj] + bo[0], acc[1][jj] + bo[1],
                                acc[2][jj] + bo[2], acc[3][jj] + bo[3]);
        float4 r1 = make_float4(acc[4][jj] + bo[4], acc[5][jj] + bo[5],
                                acc[6][jj] + bo[6], acc[7][jj] + bo[7]);
        *reinterpret_cast<float4*>(opx)     = r0;
        *reinterpret_cast<float4*>(opx + 4) = r1;
    }
}

// ---------------------------------------------------------------------------
extern "C" void kernel_launch(void* const* d_in, const int* in_sizes, int n_in,
                              void* d_out, int out_size)
{
    const float* vol   = (const float*)d_in[0];  // (4,128,128,32)
    const float* w_off = (const float*)d_in[1];  // (5,5,32,100)
    const float* b_off = (const float*)d_in[2];  // (100,)
    const float* w_dcn = (const float*)d_in[3];  // (25,32,64)
    const float* b_dcn = (const float*)d_in[4];  // (64,)
    float* out = (float*)d_out;                  // (4,120,120,64)

    dim3 gA(OW_ / 8, OH_ / 4, B_);   // (15, 30, 4)
    offset_conv_kernel<<<gA, 200>>>(vol, w_off, b_off);

    dim3 gB(OW_ / 8, OH_ / 8, B_);   // (15, 15, 4)
    dcn_kernel<<<gB, 128>>>(vol, w_dcn, b_dcn, out);
}

// round 3
// speedup vs baseline: 1.6581x; 1.0948x over previous
#include <cuda_runtime.h>

// Problem constants
#define H_   128
#define W_   128
#define C_   32
#define B_   4
#define OH_  120
#define OW_  120
#define OCH_ 100
#define F_   64

__device__ float g_offbuf[(size_t)B_ * OH_ * OW_ * OCH_];

// ---- packed f32x2 helpers (sm_103a FFMA2 path, not emitted by ptxas) ------
typedef unsigned long long u64t;

__device__ __forceinline__ u64t ffma2(u64t a, u64t b, u64t c) {
    u64t d;
    asm("fma.rn.f32x2 %0, %1, %2, %3;" : "=l"(d) : "l"(a), "l"(b), "l"(c));
    return d;
}
__device__ __forceinline__ u64t fmul2(u64t a, u64t b) {
    u64t d;
    asm("mul.rn.f32x2 %0, %1, %2;" : "=l"(d) : "l"(a), "l"(b));
    return d;
}
__device__ __forceinline__ u64t dup2(float x) {
    u64t d; unsigned xi = __float_as_uint(x);
    asm("mov.b64 %0, {%1, %1};" : "=l"(d) : "r"(xi));
    return d;
}
__device__ __forceinline__ float2 up2(u64t v) {
    float2 f;
    asm("mov.b64 {%0, %1}, %2;" : "=f"(f.x), "=f"(f.y) : "l"(v));
    return f;
}
union f4u { float4 f; ulonglong2 u; };

// ---------------------------------------------------------------------------
// Kernel A: dense dilated 5x5 conv -> 100 offset channels.
// Tile 8x4 px, 200 threads, thread tile 4ch x 4px, FFMA2 inner loop.
// ---------------------------------------------------------------------------
__global__ __launch_bounds__(200)
void offset_conv_kernel(const float* __restrict__ vol,
                        const float* __restrict__ w_off,
                        const float* __restrict__ b_off)
{
    __shared__ float patch[12 * 16 * 32];
    __shared__ float ws[32 * 100];
    __shared__ float Bs[32 * 33];

    const int tid = threadIdx.x;
    const int ox0 = blockIdx.x * 8;
    const int oy0 = blockIdx.y * 4;
    const int b   = blockIdx.z;

    for (int idx = tid; idx < 1536; idx += 200) {
        int row = idx >> 7;
        int rem = idx & 127;
        const float4* src = reinterpret_cast<const float4*>(
            vol + ((size_t)((b * H_ + oy0 + row) * W_ + ox0)) * C_);
        reinterpret_cast<float4*>(patch)[row * 128 + rem] = src[rem];
    }

    const int tm = tid % 25;
    const int tn = tid / 25;

    u64t acc2[2][4];   // [ch-pair][px]
#pragma unroll
    for (int i = 0; i < 2; ++i)
#pragma unroll
        for (int jj = 0; jj < 4; ++jj) acc2[i][jj] = 0ull;

    for (int k = 0; k < 25; ++k) {
        __syncthreads();
        for (int idx = tid; idx < 3200; idx += 200) {
            int c  = idx / 100;
            int ch = idx - c * 100;
            ws[c * 100 + ch] = w_off[(k * 32 + c) * 100 + ch];
        }
        const int fy2 = (k / 5) * 2, fx2 = (k % 5) * 2;
        for (int idx = tid; idx < 1024; idx += 200) {
            int c = idx & 31;
            int p = idx >> 5;
            int ty = p >> 3, tx = p & 7;
            Bs[c * 33 + p] = patch[((ty + fy2) * 16 + (tx + fx2)) * 32 + c];
        }
        __syncthreads();

#pragma unroll 8
        for (int c = 0; c < 32; ++c) {
            ulonglong2 Av = *reinterpret_cast<const ulonglong2*>(&ws[c * 100 + 4 * tm]);
            u64t ap[2] = {Av.x, Av.y};
            u64t bp[4];
#pragma unroll
            for (int jj = 0; jj < 4; ++jj) bp[jj] = dup2(Bs[c * 33 + 4 * tn + jj]);
#pragma unroll
            for (int i = 0; i < 2; ++i)
#pragma unroll
                for (int jj = 0; jj < 4; ++jj)
                    acc2[i][jj] = ffma2(ap[i], bp[jj], acc2[i][jj]);
        }
    }

    const int ch0 = 4 * tm;
    const float bo0 = b_off[ch0], bo1 = b_off[ch0 + 1], bo2 = b_off[ch0 + 2], bo3 = b_off[ch0 + 3];
#pragma unroll
    for (int jj = 0; jj < 4; ++jj) {
        int p  = 4 * tn + jj;
        int oy = oy0 + (p >> 3), ox = ox0 + (p & 7);
        float2 lo = up2(acc2[0][jj]);
        float2 hi = up2(acc2[1][jj]);
        float4 r = make_float4(lo.x + bo0, lo.y + bo1, hi.x + bo2, hi.y + bo3);
        *reinterpret_cast<float4*>(
            &g_offbuf[((size_t)((b * OH_ + oy) * OW_ + ox)) * OCH_ + ch0]) = r;
    }
}

// ---------------------------------------------------------------------------
// Kernel B: deformable gather + grouped conv, FFMA2 GEMM + blend.
// Tile 8y x 8x = 64 px, 128 threads, grid (15,15,4).
// ---------------------------------------------------------------------------
#define SS_P   36
#define SS_G   2320
#define WK_R   68

__global__ __launch_bounds__(128)
void dcn_kernel(const float* __restrict__ vol,
                const float* __restrict__ w_dcn,
                const float* __restrict__ b_dcn,
                float* __restrict__ out)
{
    __shared__ float wks[32 * WK_R];
    __shared__ float Ss[2 * SS_G];

    const int tid  = threadIdx.x;
    const int lane = tid & 31;
    const int warp = tid >> 5;
    const int ox0 = blockIdx.x * 8;
    const int oy0 = blockIdx.y * 8;
    const int b   = blockIdx.z;

    const int om  = tid & 7;
    const int pn  = tid >> 3;
    const int myg = om >> 2;

    const int q = lane >> 3;
    const int j = lane & 7;
    const int sBase = warp * 32;

    const float* volb = vol + (size_t)b * (H_ * W_ * C_);
    const float* offb = g_offbuf + ((size_t)(b * OH_ + oy0) * OW_ + ox0) * OCH_;

    u64t acc2[4][4];   // [out-pair][px]
#pragma unroll
    for (int i = 0; i < 4; ++i)
#pragma unroll
        for (int jj = 0; jj < 4; ++jj) acc2[i][jj] = 0ull;

    for (int k = 0; k < 25; ++k) {
        __syncthreads();

        const float* wsrc = w_dcn + k * 2048;
        for (int idx = tid; idx < 2048; idx += 128) {
            int c = idx >> 6, o = idx & 63;
            wks[c * WK_R + o + ((o & 32) >> 3)] = wsrc[idx];
        }

        const int fy = k / 5, fx = k - fy * 5;
        const float dky = (float)((fy - 2) * 2);
        const float dkx = (float)((fx - 2) * 2);

#pragma unroll
        for (int pass = 0; pass < 8; ++pass) {
            int s = sBase + pass * 4 + q;
            int p = s & 63, g = s >> 6;
            int pyi = p >> 3, pxi = p & 7;

            const float* op = offb + (pyi * OW_ + pxi) * OCH_ + k * 4 + g;
            float offy = op[0];
            float offx = op[2];

            float py = (float)(oy0 + pyi + 4) + dky + offy;
            float px = (float)(ox0 + pxi + 4) + dkx + offx;
            py = fminf(fmaxf(py, 0.0f), 127.0f);
            px = fminf(fmaxf(px, 0.0f), 127.0f);
            float y0f = fminf(floorf(py), 126.0f);
            float x0f = fminf(floorf(px), 126.0f);
            float wy = py - y0f, wx = px - x0f;
            int y0 = (int)y0f, x0 = (int)x0f;

            const float4* r0 = reinterpret_cast<const float4*>(
                volb + ((size_t)(y0 * W_ + x0)) * C_);
            f4u L0, L1, L2, L3;
            L0.f = r0[j];
            L1.f = r0[j + 8];
            L2.f = r0[j + 1024];
            L3.f = r0[j + 1032];

            u64t c00p = dup2((1.0f - wy) * (1.0f - wx));
            u64t c01p = dup2((1.0f - wy) * wx);
            u64t c10p = dup2(wy * (1.0f - wx));
            u64t c11p = dup2(wy * wx);

            ulonglong2 sv;
            sv.x = ffma2(L0.u.x, c00p, ffma2(L1.u.x, c01p,
                       ffma2(L2.u.x, c10p, fmul2(L3.u.x, c11p))));
            sv.y = ffma2(L0.u.y, c00p, ffma2(L1.u.y, c01p,
                       ffma2(L2.u.y, c10p, fmul2(L3.u.y, c11p))));

            *reinterpret_cast<ulonglong2*>(&Ss[g * SS_G + p * SS_P + j * 4]) = sv;
        }
        __syncthreads();

        const float* Sg   = Ss + myg * SS_G;
        const float* wrow = wks + om * 8 + ((om & 4) ? 4 : 0);
#pragma unroll
        for (int c = 0; c < 32; ++c) {
            ulonglong2 A0 = *reinterpret_cast<const ulonglong2*>(&wrow[c * WK_R]);
            ulonglong2 A1 = *reinterpret_cast<const ulonglong2*>(&wrow[c * WK_R + 4]);
            u64t ap[4] = {A0.x, A0.y, A1.x, A1.y};
            u64t bp[4];
            bp[0] = dup2(Sg[(pn     ) * SS_P + c]);
            bp[1] = dup2(Sg[(pn + 16) * SS_P + c]);
            bp[2] = dup2(Sg[(pn + 32) * SS_P + c]);
            bp[3] = dup2(Sg[(pn + 48) * SS_P + c]);
#pragma unroll
            for (int i = 0; i < 4; ++i)
#pragma unroll
                for (int jj = 0; jj < 4; ++jj)
                    acc2[i][jj] = ffma2(ap[i], bp[jj], acc2[i][jj]);
        }
    }

    const int o0 = om * 8;
    float bo[8];
#pragma unroll
    for (int i = 0; i < 8; ++i) bo[i] = b_dcn[o0 + i];
#pragma unroll
    for (int jj = 0; jj < 4; ++jj) {
        int p  = pn + jj * 16;
        int oy = oy0 + (p >> 3), ox = ox0 + (p & 7);
        float* opx = out + ((size_t)((b * OH_ + oy) * OW_ + ox)) * F_ + o0;
        float2 p0 = up2(acc2[0][jj]);
        float2 p1 = up2(acc2[1][jj]);
        float2 p2 = up2(acc2[2][jj]);
        float2 p3 = up2(acc2[3][jj]);
        float4 r0 = make_float4(p0.x + bo[0], p0.y + bo[1], p1.x + bo[2], p1.y + bo[3]);
        float4 r1 = make_float4(p2.x + bo[4], p2.y + bo[5], p3.x + bo[6], p3.y + bo[7]);
        *reinterpret_cast<float4*>(opx)     = r0;
        *reinterpret_cast<float4*>(opx + 4) = r1;
    }
}

// ---------------------------------------------------------------------------
extern "C" void kernel_launch(void* const* d_in, const int* in_sizes, int n_in,
                              void* d_out, int out_size)
{
    const float* vol   = (const float*)d_in[0];
    const float* w_off = (const float*)d_in[1];
    const float* b_off = (const float*)d_in[2];
    const float* w_dcn = (const float*)d_in[3];
    const float* b_dcn = (const float*)d_in[4];
    float* out = (float*)d_out;

    dim3 gA(OW_ / 8, OH_ / 4, B_);
    offset_conv_kernel<<<gA, 200>>>(vol, w_off, b_off);

    dim3 gB(OW_ / 8, OH_ / 8, B_);
    dcn_kernel<<<gB, 128>>>(vol, w_dcn, b_dcn, out);
}